// round 4
// baseline (speedup 1.0000x reference)
#include <cuda_runtime.h>

namespace {

constexpr int Bn  = 32768;
constexpr int Nn  = 512;
constexpr int Fn  = 8;
constexpr int On  = 32;
constexpr int T   = 128;        // threads per block
constexpr int K   = Nn / T;     // 4 neighbors per thread

__global__ __launch_bounds__(T)
void gat_kernel(const float* __restrict__ ego,          // [B, F]
                const float* __restrict__ neigh,        // [B, N, F]
                const int*   __restrict__ mask,         // [B, N] (bool -> int32)
                const float* __restrict__ W_ego,        // [F, F]
                const float* __restrict__ b_ego,        // [F]
                const float* __restrict__ w_attn,       // [2F]
                const float* __restrict__ b_attn,       // [1]
                const float* __restrict__ W_out,        // [F, OUT]
                const float* __restrict__ b_out,        // [OUT]
                float* __restrict__ out)                // [B, OUT]
{
    const int b    = blockIdx.x;
    const int t    = threadIdx.x;
    const int warp = t >> 5;
    const int lane = t & 31;

    __shared__ float s_wmax[4];
    __shared__ float s_wsum[4];
    __shared__ float s_part[4][Fn];
    __shared__ float s_tb;
    __shared__ float s_agg[Fn];

    // ---- Load this row's neighbors into registers (read HBM exactly once).
    // Thread t owns neighbor rows {t, t+128, t+256, t+384}. Each row = 2 float4.
    // Per load instruction a warp touches 32*16B = 512B contiguous: fully coalesced.
    const float4* np4 = reinterpret_cast<const float4*>(neigh + (size_t)b * (Nn * Fn));
    float4 na[K], nb[K];
    int m[K];
#pragma unroll
    for (int k = 0; k < K; k++) {
        const int r = t + k * T;
        na[k] = np4[2 * r];
        nb[k] = np4[2 * r + 1];
        m[k]  = mask[(size_t)b * Nn + r];
    }

    // ---- Per-row ego scalar: t_b = (ego@W_ego + b_ego) . wa_e + b_attn.
    // All operands tiny & cache-resident; one thread does it.
    if (t == 0) {
        float tb = b_attn[0];
#pragma unroll
        for (int j = 0; j < Fn; j++) {
            float p = b_ego[j];
#pragma unroll
            for (int i = 0; i < Fn; i++)
                p += ego[(size_t)b * Fn + i] * W_ego[i * Fn + j];
            tb += p * w_attn[j];
        }
        s_tb = tb;
    }

    // wa_n (w_attn[8..15]) — cached, every thread loads its own copy.
    const float w0 = w_attn[Fn + 0], w1 = w_attn[Fn + 1];
    const float w2 = w_attn[Fn + 2], w3 = w_attn[Fn + 3];
    const float w4 = w_attn[Fn + 4], w5 = w_attn[Fn + 5];
    const float w6 = w_attn[Fn + 6], w7 = w_attn[Fn + 7];

    __syncthreads();
    const float tb = s_tb;

    // ---- Scores + masked max.
    constexpr float NEG = -1e9f;
    float sc[K];
    float mx = NEG;
#pragma unroll
    for (int k = 0; k < K; k++) {
        float s = tb
                + na[k].x * w0 + na[k].y * w1 + na[k].z * w2 + na[k].w * w3
                + nb[k].x * w4 + nb[k].y * w5 + nb[k].z * w6 + nb[k].w * w7;
        sc[k] = m[k] ? s : NEG;
        mx = fmaxf(mx, sc[k]);
    }
#pragma unroll
    for (int o = 16; o; o >>= 1)
        mx = fmaxf(mx, __shfl_xor_sync(0xffffffffu, mx, o));
    if (lane == 0) s_wmax[warp] = mx;
    __syncthreads();
    mx = fmaxf(fmaxf(s_wmax[0], s_wmax[1]), fmaxf(s_wmax[2], s_wmax[3]));

    // ---- exp + sum. Masked lanes contribute exact 0 (reference: exp(-1e9 - max)
    // underflows to 0 in fp32, then * mask makes it exactly 0 anyway).
    float e[K];
    float sum = 0.f;
#pragma unroll
    for (int k = 0; k < K; k++) {
        e[k] = m[k] ? __expf(sc[k] - mx) : 0.f;
        sum += e[k];
    }
#pragma unroll
    for (int o = 16; o; o >>= 1)
        sum += __shfl_xor_sync(0xffffffffu, sum, o);
    if (lane == 0) s_wsum[warp] = sum;

    // ---- Unnormalized weighted aggregation: acc[f] = sum_k e_k * n_k[f].
    float acc[Fn];
#pragma unroll
    for (int f = 0; f < Fn; f++) acc[f] = 0.f;
#pragma unroll
    for (int k = 0; k < K; k++) {
        const float ek = e[k];
        acc[0] += ek * na[k].x;  acc[1] += ek * na[k].y;
        acc[2] += ek * na[k].z;  acc[3] += ek * na[k].w;
        acc[4] += ek * nb[k].x;  acc[5] += ek * nb[k].y;
        acc[6] += ek * nb[k].z;  acc[7] += ek * nb[k].w;
    }
#pragma unroll
    for (int o = 16; o; o >>= 1) {
#pragma unroll
        for (int f = 0; f < Fn; f++)
            acc[f] += __shfl_xor_sync(0xffffffffu, acc[f], o);
    }
    if (lane == 0) {
#pragma unroll
        for (int f = 0; f < Fn; f++) s_part[warp][f] = acc[f];
    }
    __syncthreads();

    // ---- Normalize (guard all-masked row: sum==0 -> agg=0 -> out=b_out).
    const float tot  = s_wsum[0] + s_wsum[1] + s_wsum[2] + s_wsum[3];
    const float rinv = (tot > 0.f) ? (1.f / tot) : 0.f;
    if (t < Fn) {
        s_agg[t] = (s_part[0][t] + s_part[1][t] + s_part[2][t] + s_part[3][t]) * rinv;
    }
    __syncthreads();

    // ---- Output GEMV: out[b, o] = agg . W_out[:, o] + b_out[o].
    if (t < On) {
        float v = b_out[t];
#pragma unroll
        for (int f = 0; f < Fn; f++)
            v += s_agg[f] * W_out[f * On + t];
        out[(size_t)b * On + t] = v;
    }
}

} // namespace

extern "C" void kernel_launch(void* const* d_in, const int* in_sizes, int n_in,
                              void* d_out, int out_size)
{
    const float* ego    = (const float*)d_in[0];
    const float* neigh  = (const float*)d_in[1];
    const int*   mask   = (const int*)d_in[2];
    const float* W_ego  = (const float*)d_in[3];
    const float* b_ego  = (const float*)d_in[4];
    const float* w_attn = (const float*)d_in[5];
    const float* b_attn = (const float*)d_in[6];
    const float* W_out  = (const float*)d_in[7];
    const float* b_out  = (const float*)d_in[8];
    float*       out    = (float*)d_out;

    gat_kernel<<<Bn, T>>>(ego, neigh, mask, W_ego, b_ego, w_attn, b_attn,
                          W_out, b_out, out);
}